// round 12
// baseline (speedup 1.0000x reference)
#include <cuda_runtime.h>
#include <cuda_bf16.h>
#include <cstdint>

#define B 8
#define C 256
#define N 4096            // 64*64
#define G 8
#define CG 32             // channels per group
#define EPS 1e-5f
#define SCALE 0.0625f     // 1/sqrt(256)

// ---------------- scratch ----------------------------------------------------
__device__ float         g_xn[(size_t)B * C * N];   // groupnormed x, [b][c][n]
__device__ __nv_bfloat16 g_q[(size_t)B * N * C];    // Q [b][n][c]
__device__ __nv_bfloat16 g_k[(size_t)B * N * C];    // K [b][n][c]
__device__ __nv_bfloat16 g_v[(size_t)B * C * N];    // V [b][c][n]  (transposed)
__device__ float         g_att[(size_t)B * N * C];  // attention out [b][n][c]
__device__ float         g_mean[B * G];
__device__ float         g_rstd[B * G];

// ---------------- mma / ldmatrix helpers --------------------------------------
__device__ __forceinline__ uint32_t f2tf32(float x) {
    uint32_t r;
    asm("cvt.rna.tf32.f32 %0, %1;" : "=r"(r) : "f"(x));
    return r;
}

__device__ __forceinline__ void mma_tf32(float* d, const uint32_t* a, const uint32_t* b) {
    asm volatile(
        "mma.sync.aligned.m16n8k8.row.col.f32.tf32.tf32.f32 "
        "{%0,%1,%2,%3}, {%4,%5,%6,%7}, {%8,%9}, {%0,%1,%2,%3};\n"
        : "+f"(d[0]), "+f"(d[1]), "+f"(d[2]), "+f"(d[3])
        : "r"(a[0]), "r"(a[1]), "r"(a[2]), "r"(a[3]),
          "r"(b[0]), "r"(b[1]));
}

__device__ __forceinline__ void mma_bf16(float* d, const uint32_t* a,
                                         uint32_t b0, uint32_t b1) {
    asm volatile(
        "mma.sync.aligned.m16n8k16.row.col.f32.bf16.bf16.f32 "
        "{%0,%1,%2,%3}, {%4,%5,%6,%7}, {%8,%9}, {%0,%1,%2,%3};\n"
        : "+f"(d[0]), "+f"(d[1]), "+f"(d[2]), "+f"(d[3])
        : "r"(a[0]), "r"(a[1]), "r"(a[2]), "r"(a[3]),
          "r"(b0), "r"(b1));
}

__device__ __forceinline__ void ldsm_x4(uint32_t& r0, uint32_t& r1,
                                        uint32_t& r2, uint32_t& r3, uint32_t addr) {
    asm volatile("ldmatrix.sync.aligned.m8n8.x4.shared.b16 {%0,%1,%2,%3}, [%4];"
                 : "=r"(r0), "=r"(r1), "=r"(r2), "=r"(r3) : "r"(addr));
}

__device__ __forceinline__ uint32_t smem_u32(const void* p) {
    return (uint32_t)__cvta_generic_to_shared(p);
}

// ---------------- kernel 1: groupnorm stats ----------------------------------
__global__ void gn_stats(const float* __restrict__ x) {
    int bg = blockIdx.x;
    const float4* p = (const float4*)(x + (size_t)bg * CG * N);
    float s = 0.f, ss = 0.f;
    for (int i = threadIdx.x; i < (CG * N) / 4; i += blockDim.x) {
        float4 v = p[i];
        s  += v.x + v.y + v.z + v.w;
        ss += v.x * v.x + v.y * v.y + v.z * v.z + v.w * v.w;
    }
    for (int o = 16; o > 0; o >>= 1) {
        s  += __shfl_down_sync(0xffffffffu, s, o);
        ss += __shfl_down_sync(0xffffffffu, ss, o);
    }
    __shared__ float rs[8], rss[8];
    int wid = threadIdx.x >> 5, lid = threadIdx.x & 31;
    if (lid == 0) { rs[wid] = s; rss[wid] = ss; }
    __syncthreads();
    if (threadIdx.x == 0) {
        float ts = 0.f, tss = 0.f;
        for (int i = 0; i < 8; i++) { ts += rs[i]; tss += rss[i]; }
        float inv = 1.0f / (float)(CG * N);
        float mean = ts * inv;
        float var = tss * inv - mean * mean;
        g_mean[bg] = mean;
        g_rstd[bg] = rsqrtf(var + EPS);
    }
}

// ---------------- kernel 2: groupnorm apply ----------------------------------
__global__ void gn_apply(const float* __restrict__ x,
                         const float* __restrict__ sc,
                         const float* __restrict__ bi) {
    int i = blockIdx.x * blockDim.x + threadIdx.x;
    int e = i << 2;
    int c = (e >> 12) & (C - 1);
    int bg = e >> 17;
    float m = g_mean[bg], r = g_rstd[bg];
    float a = sc[c] * r;
    float b = bi[c] - m * a;
    float4 v = ((const float4*)x)[i];
    float4 o;
    o.x = v.x * a + b; o.y = v.y * a + b; o.z = v.z * a + b; o.w = v.w * a + b;
    ((float4*)g_xn)[i] = o;
}

// ---------------- kernel 3: QKV GEMM, tf32 mma; writes bf16 ------------------
__global__ __launch_bounds__(256) void qkv_gemm(const float* __restrict__ W,
                                                const float* __restrict__ bias) {
    __shared__ uint32_t Ws[64 * 36];
    __shared__ uint32_t Xs[32 * 72];
    int b  = blockIdx.z;
    int o0 = blockIdx.y * 64;
    int n0 = blockIdx.x * 64;
    const float* Xb = g_xn + (size_t)b * C * N;

    int tid  = threadIdx.x;
    int warp = tid >> 5, lane = tid & 31;
    int gr = lane >> 2, t = lane & 3;
    int r0 = 16 * (warp & 3);
    int c0 = 32 * (warp >> 2);

    float acc[4][4] = {};
    for (int k0 = 0; k0 < C; k0 += 32) {
        for (int i = tid; i < 64 * 32; i += 256) {
            int rr = i >> 5, cc = i & 31;
            Ws[rr * 36 + cc] = f2tf32(W[(size_t)(o0 + rr) * C + k0 + cc]);
        }
        for (int i = tid; i < 32 * 64; i += 256) {
            int kk = i >> 6, nn = i & 63;
            Xs[kk * 72 + nn] = f2tf32(Xb[(size_t)(k0 + kk) * N + n0 + nn]);
        }
        __syncthreads();
#pragma unroll
        for (int ks = 0; ks < 4; ks++) {
            int kb = ks * 8;
            uint32_t a[4];
            a[0] = Ws[(r0 + gr) * 36 + kb + t];
            a[1] = Ws[(r0 + gr + 8) * 36 + kb + t];
            a[2] = Ws[(r0 + gr) * 36 + kb + t + 4];
            a[3] = Ws[(r0 + gr + 8) * 36 + kb + t + 4];
#pragma unroll
            for (int nt = 0; nt < 4; nt++) {
                int nb = c0 + nt * 8;
                uint32_t bb[2];
                bb[0] = Xs[(kb + t) * 72 + nb + gr];
                bb[1] = Xs[(kb + t + 4) * 72 + nb + gr];
                mma_tf32(acc[nt], a, bb);
            }
        }
        __syncthreads();
    }
    int o_a = o0 + r0 + gr, o_b = o_a + 8;
    float bv_a = bias[o_a], bv_b = bias[o_b];
    if (o0 < 512) {
        __nv_bfloat16* dst = (o0 < 256) ? g_q : g_k;
        int oc_a = o_a & 255, oc_b = o_b & 255;
#pragma unroll
        for (int nt = 0; nt < 4; nt++) {
            int n = n0 + c0 + nt * 8 + 2 * t;
            dst[((size_t)b * N + n)     * C + oc_a] = __float2bfloat16(acc[nt][0] + bv_a);
            dst[((size_t)b * N + n + 1) * C + oc_a] = __float2bfloat16(acc[nt][1] + bv_a);
            dst[((size_t)b * N + n)     * C + oc_b] = __float2bfloat16(acc[nt][2] + bv_b);
            dst[((size_t)b * N + n + 1) * C + oc_b] = __float2bfloat16(acc[nt][3] + bv_b);
        }
    } else {
        int oc_a = o_a - 512, oc_b = o_b - 512;
#pragma unroll
        for (int nt = 0; nt < 4; nt++) {
            int n = n0 + c0 + nt * 8 + 2 * t;
            __nv_bfloat162 va = __floats2bfloat162_rn(acc[nt][0] + bv_a, acc[nt][1] + bv_a);
            __nv_bfloat162 vb = __floats2bfloat162_rn(acc[nt][2] + bv_b, acc[nt][3] + bv_b);
            *(__nv_bfloat162*)&g_v[((size_t)b * C + oc_a) * N + n] = va;
            *(__nv_bfloat162*)&g_v[((size_t)b * C + oc_b) * N + n] = vb;
        }
    }
}

// ---------------- kernel 4: flash attention, register-resident FA2 -----------
// Br = 128, Bc = 64, 8 warps; warp w owns rows 16w..16w+15 (ALL 64 S columns).
// Online softmax + P entirely in registers. O = 16x256 f32 per warp (128 regs).
// Smem: union buffer 27.6KB { Qs[128][36] + Ks[64][36] } alias { Vs[256][20] }.
__global__ __launch_bounds__(256, 1) void flash_kernel() {
    __shared__ __align__(16) uint32_t SBUF[128 * 36 + 64 * 36];   // 6912 u32
    uint32_t* Qs = SBUF;
    uint32_t* Ks = SBUF + 128 * 36;
    uint32_t* Vs = SBUF;                  // 256*20 = 5120 <= 6912

    int b  = blockIdx.y;
    int i0 = blockIdx.x * 128;
    const __nv_bfloat16* Qb = g_q + (size_t)b * N * C;
    const __nv_bfloat16* Kb = g_k + (size_t)b * N * C;
    const uint32_t* Vb32 = (const uint32_t*)(g_v + (size_t)b * C * N);

    int tid  = threadIdx.x;
    int warp = tid >> 5, lane = tid & 31;
    int gr = lane >> 2, t = lane & 3;
    int r0 = 16 * warp;                  // this warp's row base (0..112)

    // ldmatrix lane addresses
    int l15 = lane & 15, l7 = lane & 7;
    int hi16 = lane >> 4;
    int bsel = (lane >> 3) & 1;
    uint32_t qa_addr = smem_u32(Qs) + 4u * ((r0 + l15) * 36 + 4 * hi16);
    uint32_t kb_addr = smem_u32(Ks) + 4u * ((l7 + 8 * hi16) * 36 + 4 * bsel);
    uint32_t vb_addr = smem_u32(Vs) + 4u * ((l7 + 8 * hi16) * 20 + 4 * bsel);

    float O[32][4];
#pragma unroll
    for (int i = 0; i < 32; i++)
#pragma unroll
        for (int j = 0; j < 4; j++) O[i][j] = 0.f;
    float m0 = -3.4e38f, m1 = -3.4e38f, l0 = 0.f, l1 = 0.f;

    for (int j0 = 0; j0 < N; j0 += 64) {
        // ---------- S = Q K^T  (4 chunks of 64 channels) ----------
        float accs[8][4];
#pragma unroll
        for (int i = 0; i < 8; i++)
#pragma unroll
            for (int j = 0; j < 4; j++) accs[i][j] = 0.f;

        for (int k0 = 0; k0 < C; k0 += 64) {
            // stage Q chunk (128 rows x 8 uint4) + K chunk (64 rows x 8 uint4)
            for (int i = tid; i < 1024; i += 256) {
                int rr = i >> 3, cc = i & 7;
                ((uint4*)(Qs + rr * 36))[cc] =
                    ((const uint4*)(Qb + (size_t)(i0 + rr) * C + k0))[cc];
            }
            for (int i = tid; i < 512; i += 256) {
                int rr = i >> 3, cc = i & 7;
                ((uint4*)(Ks + rr * 36))[cc] =
                    ((const uint4*)(Kb + (size_t)(j0 + rr) * C + k0))[cc];
            }
            __syncthreads();
#pragma unroll
            for (int ks = 0; ks < 4; ks++) {
                uint32_t a[4];
                ldsm_x4(a[0], a[1], a[2], a[3], qa_addr + 32 * ks);
#pragma unroll
                for (int pr = 0; pr < 4; pr++) {      // 4 ldsm = 8 n-tiles
                    uint32_t b0, b1, b2, b3;
                    ldsm_x4(b0, b1, b2, b3, kb_addr + 2304 * pr + 32 * ks);
                    mma_bf16(accs[2 * pr],     a, b0, b1);
                    mma_bf16(accs[2 * pr + 1], a, b2, b3);
                }
            }
            __syncthreads();
        }

        // ---------- online softmax in registers ----------
        // row gr: accs[j][0..1]; row gr+8: accs[j][2..3]; reduction over quad.
        float mx0 = -3.4e38f, mx1 = -3.4e38f;
#pragma unroll
        for (int j = 0; j < 8; j++) {
            mx0 = fmaxf(mx0, fmaxf(accs[j][0], accs[j][1]));
            mx1 = fmaxf(mx1, fmaxf(accs[j][2], accs[j][3]));
        }
        mx0 = fmaxf(mx0, __shfl_xor_sync(0xffffffffu, mx0, 1));
        mx0 = fmaxf(mx0, __shfl_xor_sync(0xffffffffu, mx0, 2));
        mx1 = fmaxf(mx1, __shfl_xor_sync(0xffffffffu, mx1, 1));
        mx1 = fmaxf(mx1, __shfl_xor_sync(0xffffffffu, mx1, 2));
        float mn0 = fmaxf(m0, mx0 * SCALE);
        float mn1 = fmaxf(m1, mx1 * SCALE);
        float al0 = __expf(m0 - mn0);
        float al1 = __expf(m1 - mn1);
        m0 = mn0; m1 = mn1;
        float s0 = 0.f, s1 = 0.f;
#pragma unroll
        for (int j = 0; j < 8; j++) {
            accs[j][0] = __expf(accs[j][0] * SCALE - m0);
            accs[j][1] = __expf(accs[j][1] * SCALE - m0);
            accs[j][2] = __expf(accs[j][2] * SCALE - m1);
            accs[j][3] = __expf(accs[j][3] * SCALE - m1);
            s0 += accs[j][0] + accs[j][1];
            s1 += accs[j][2] + accs[j][3];
        }
        s0 += __shfl_xor_sync(0xffffffffu, s0, 1);
        s0 += __shfl_xor_sync(0xffffffffu, s0, 2);
        s1 += __shfl_xor_sync(0xffffffffu, s1, 1);
        s1 += __shfl_xor_sync(0xffffffffu, s1, 2);
        l0 = l0 * al0 + s0;
        l1 = l1 * al1 + s1;
        // rescale O
#pragma unroll
        for (int nt = 0; nt < 32; nt++) {
            O[nt][0] *= al0; O[nt][1] *= al0;
            O[nt][2] *= al1; O[nt][3] *= al1;
        }

        // ---------- O += P V  (P in regs; 2 V-chunks of 32 seq) ----------
        for (int vc = 0; vc < 2; vc++) {
            int sbase = (j0 + 32 * vc) >> 1;
            for (int i = tid; i < 1024; i += 256) {
                int ch = i >> 2, q = (i & 3) << 2;
                *(uint4*)(Vs + ch * 20 + q) =
                    *(const uint4*)(Vb32 + (size_t)ch * (N / 2) + sbase + q);
            }
            __syncthreads();
#pragma unroll
            for (int sub = 0; sub < 2; sub++) {
                int kk = 2 * vc + sub;        // k16-tile within Bc=64
                uint32_t a[4];
                __nv_bfloat162 p0 = __floats2bfloat162_rn(accs[2 * kk][0], accs[2 * kk][1]);
                __nv_bfloat162 p1 = __floats2bfloat162_rn(accs[2 * kk][2], accs[2 * kk][3]);
                __nv_bfloat162 p2 = __floats2bfloat162_rn(accs[2 * kk + 1][0], accs[2 * kk + 1][1]);
                __nv_bfloat162 p3 = __floats2bfloat162_rn(accs[2 * kk + 1][2], accs[2 * kk + 1][3]);
                a[0] = *(uint32_t*)&p0;
                a[1] = *(uint32_t*)&p1;
                a[2] = *(uint32_t*)&p2;
                a[3] = *(uint32_t*)&p3;
#pragma unroll
                for (int ntp = 0; ntp < 16; ntp++) {
                    uint32_t v0, v1, v2, v3;
                    ldsm_x4(v0, v1, v2, v3, vb_addr + 1280 * ntp + 32 * sub);
                    mma_bf16(O[2 * ntp],     a, v0, v1);
                    mma_bf16(O[2 * ntp + 1], a, v2, v3);
                }
            }
            __syncthreads();
        }
    }

    // ---------- finalize ----------
    float inv0 = 1.0f / l0;
    float inv1 = 1.0f / l1;
    float* Ab = g_att + (size_t)b * N * C;
#pragma unroll
    for (int nt = 0; nt < 32; nt++) {
        int col = nt * 8 + 2 * t;
        float2 v0 = make_float2(O[nt][0] * inv0, O[nt][1] * inv0);
        float2 v1 = make_float2(O[nt][2] * inv1, O[nt][3] * inv1);
        *(float2*)&Ab[(size_t)(i0 + r0 + gr) * C + col]     = v0;
        *(float2*)&Ab[(size_t)(i0 + r0 + gr + 8) * C + col] = v1;
    }
}

// ---------------- kernel 5: proj GEMM + bias + residual, tf32 mma ------------
__global__ __launch_bounds__(256) void proj_gemm(const float* __restrict__ W,
                                                 const float* __restrict__ bias,
                                                 const float* __restrict__ x,
                                                 float* __restrict__ out) {
    __shared__ uint32_t Ws[64 * 36];
    __shared__ uint32_t Bs[32 * 68];
    int b  = blockIdx.z;
    int o0 = blockIdx.y * 64;
    int n0 = blockIdx.x * 64;
    const float* Ab = g_att + (size_t)b * N * C;

    int tid  = threadIdx.x;
    int warp = tid >> 5, lane = tid & 31;
    int gr = lane >> 2, t = lane & 3;
    int r0 = 16 * (warp & 3);
    int c0 = 32 * (warp >> 2);

    float acc[4][4] = {};
    for (int k0 = 0; k0 < C; k0 += 32) {
        for (int i = tid; i < 64 * 32; i += 256) {
            int rr = i >> 5, cc = i & 31;
            Ws[rr * 36 + cc] = f2tf32(W[(size_t)(o0 + rr) * C + k0 + cc]);
        }
        for (int i = tid; i < 64 * 32; i += 256) {
            int nn = i >> 5, kk = i & 31;
            Bs[kk * 68 + nn] = f2tf32(Ab[(size_t)(n0 + nn) * C + k0 + kk]);
        }
        __syncthreads();
#pragma unroll
        for (int ks = 0; ks < 4; ks++) {
            int kb = ks * 8;
            uint32_t a[4];
            a[0] = Ws[(r0 + gr) * 36 + kb + t];
            a[1] = Ws[(r0 + gr + 8) * 36 + kb + t];
            a[2] = Ws[(r0 + gr) * 36 + kb + t + 4];
            a[3] = Ws[(r0 + gr + 8) * 36 + kb + t + 4];
#pragma unroll
            for (int nt = 0; nt < 4; nt++) {
                int nb = c0 + nt * 8;
                uint32_t bb[2];
                bb[0] = Bs[(kb + t) * 68 + nb + gr];
                bb[1] = Bs[(kb + t + 4) * 68 + nb + gr];
                mma_tf32(acc[nt], a, bb);
            }
        }
        __syncthreads();
    }
    int o_a = o0 + r0 + gr, o_b = o_a + 8;
    float bv_a = bias[o_a], bv_b = bias[o_b];
#pragma unroll
    for (int nt = 0; nt < 4; nt++) {
        int n = n0 + c0 + nt * 8 + 2 * t;
        size_t ia = ((size_t)b * C + o_a) * N + n;
        size_t ib = ((size_t)b * C + o_b) * N + n;
        float2 xa = *(const float2*)&x[ia];
        float2 xb = *(const float2*)&x[ib];
        float2 oa = make_float2(acc[nt][0] + bv_a + xa.x, acc[nt][1] + bv_a + xa.y);
        float2 ob = make_float2(acc[nt][2] + bv_b + xb.x, acc[nt][3] + bv_b + xb.y);
        *(float2*)&out[ia] = oa;
        *(float2*)&out[ib] = ob;
    }
}

// ---------------- launch ------------------------------------------------------
extern "C" void kernel_launch(void* const* d_in, const int* in_sizes, int n_in,
                              void* d_out, int out_size) {
    const float* x    = (const float*)d_in[0];
    const float* gns  = (const float*)d_in[1];
    const float* gnb  = (const float*)d_in[2];
    const float* qkvw = (const float*)d_in[3];
    const float* qkvb = (const float*)d_in[4];
    const float* pw   = (const float*)d_in[5];
    const float* pb   = (const float*)d_in[6];
    float* out = (float*)d_out;

    gn_stats<<<B * G, 256>>>(x);
    gn_apply<<<(B * C * N / 4) / 256, 256>>>(x, gns, gnb);

    dim3 gq(N / 64, (3 * C) / 64, B);
    qkv_gemm<<<gq, 256>>>(qkvw, qkvb);

    dim3 gf(N / 128, B);
    flash_kernel<<<gf, 256>>>();

    dim3 gp(N / 64, C / 64, B);
    proj_gemm<<<gp, 256>>>(pw, pb, x, out);
}

// round 15
// speedup vs baseline: 1.0860x; 1.0860x over previous
#include <cuda_runtime.h>
#include <cuda_bf16.h>
#include <cstdint>

#define B 8
#define C 256
#define N 4096            // 64*64
#define G 8
#define CG 32             // channels per group
#define EPS 1e-5f
#define SCALE 0.0625f     // 1/sqrt(256)

// ---------------- scratch ----------------------------------------------------
__device__ float         g_xn[(size_t)B * C * N];   // groupnormed x, [b][c][n]
__device__ __nv_bfloat16 g_q[(size_t)B * N * C];    // Q [b][n][c]  (pre-scaled by SCALE)
__device__ __nv_bfloat16 g_k[(size_t)B * N * C];    // K [b][n][c]
__device__ __nv_bfloat16 g_v[(size_t)B * C * N];    // V [b][c][n]  (transposed)
__device__ float         g_att[(size_t)B * N * C];  // attention out [b][n][c]
__device__ float         g_mean[B * G];
__device__ float         g_rstd[B * G];

// ---------------- mma / ldmatrix helpers --------------------------------------
__device__ __forceinline__ uint32_t f2tf32(float x) {
    uint32_t r;
    asm("cvt.rna.tf32.f32 %0, %1;" : "=r"(r) : "f"(x));
    return r;
}

__device__ __forceinline__ void mma_tf32(float* d, const uint32_t* a, const uint32_t* b) {
    asm volatile(
        "mma.sync.aligned.m16n8k8.row.col.f32.tf32.tf32.f32 "
        "{%0,%1,%2,%3}, {%4,%5,%6,%7}, {%8,%9}, {%0,%1,%2,%3};\n"
        : "+f"(d[0]), "+f"(d[1]), "+f"(d[2]), "+f"(d[3])
        : "r"(a[0]), "r"(a[1]), "r"(a[2]), "r"(a[3]),
          "r"(b[0]), "r"(b[1]));
}

__device__ __forceinline__ void mma_bf16(float* d, const uint32_t* a,
                                         uint32_t b0, uint32_t b1) {
    asm volatile(
        "mma.sync.aligned.m16n8k16.row.col.f32.bf16.bf16.f32 "
        "{%0,%1,%2,%3}, {%4,%5,%6,%7}, {%8,%9}, {%0,%1,%2,%3};\n"
        : "+f"(d[0]), "+f"(d[1]), "+f"(d[2]), "+f"(d[3])
        : "r"(a[0]), "r"(a[1]), "r"(a[2]), "r"(a[3]),
          "r"(b0), "r"(b1));
}

__device__ __forceinline__ void ldsm_x4(uint32_t& r0, uint32_t& r1,
                                        uint32_t& r2, uint32_t& r3, uint32_t addr) {
    asm volatile("ldmatrix.sync.aligned.m8n8.x4.shared.b16 {%0,%1,%2,%3}, [%4];"
                 : "=r"(r0), "=r"(r1), "=r"(r2), "=r"(r3) : "r"(addr));
}

__device__ __forceinline__ uint32_t smem_u32(const void* p) {
    return (uint32_t)__cvta_generic_to_shared(p);
}

// ---------------- kernel 1: groupnorm stats ----------------------------------
__global__ void gn_stats(const float* __restrict__ x) {
    int bg = blockIdx.x;
    const float4* p = (const float4*)(x + (size_t)bg * CG * N);
    float s = 0.f, ss = 0.f;
    for (int i = threadIdx.x; i < (CG * N) / 4; i += blockDim.x) {
        float4 v = p[i];
        s  += v.x + v.y + v.z + v.w;
        ss += v.x * v.x + v.y * v.y + v.z * v.z + v.w * v.w;
    }
    for (int o = 16; o > 0; o >>= 1) {
        s  += __shfl_down_sync(0xffffffffu, s, o);
        ss += __shfl_down_sync(0xffffffffu, ss, o);
    }
    __shared__ float rs[8], rss[8];
    int wid = threadIdx.x >> 5, lid = threadIdx.x & 31;
    if (lid == 0) { rs[wid] = s; rss[wid] = ss; }
    __syncthreads();
    if (threadIdx.x == 0) {
        float ts = 0.f, tss = 0.f;
        for (int i = 0; i < 8; i++) { ts += rs[i]; tss += rss[i]; }
        float inv = 1.0f / (float)(CG * N);
        float mean = ts * inv;
        float var = tss * inv - mean * mean;
        g_mean[bg] = mean;
        g_rstd[bg] = rsqrtf(var + EPS);
    }
}

// ---------------- kernel 2: groupnorm apply ----------------------------------
__global__ void gn_apply(const float* __restrict__ x,
                         const float* __restrict__ sc,
                         const float* __restrict__ bi) {
    int i = blockIdx.x * blockDim.x + threadIdx.x;
    int e = i << 2;
    int c = (e >> 12) & (C - 1);
    int bg = e >> 17;
    float m = g_mean[bg], r = g_rstd[bg];
    float a = sc[c] * r;
    float b = bi[c] - m * a;
    float4 v = ((const float4*)x)[i];
    float4 o;
    o.x = v.x * a + b; o.y = v.y * a + b; o.z = v.z * a + b; o.w = v.w * a + b;
    ((float4*)g_xn)[i] = o;
}

// ---------------- kernel 3: QKV GEMM, tf32 mma; writes bf16 ------------------
// Q outputs pre-multiplied by SCALE (exact power of 2 in bf16).
__global__ __launch_bounds__(256) void qkv_gemm(const float* __restrict__ W,
                                                const float* __restrict__ bias) {
    __shared__ uint32_t Ws[64 * 36];
    __shared__ uint32_t Xs[32 * 72];
    int b  = blockIdx.z;
    int o0 = blockIdx.y * 64;
    int n0 = blockIdx.x * 64;
    const float* Xb = g_xn + (size_t)b * C * N;

    int tid  = threadIdx.x;
    int warp = tid >> 5, lane = tid & 31;
    int gr = lane >> 2, t = lane & 3;
    int r0 = 16 * (warp & 3);
    int c0 = 32 * (warp >> 2);

    float acc[4][4] = {};
    for (int k0 = 0; k0 < C; k0 += 32) {
        for (int i = tid; i < 64 * 32; i += 256) {
            int rr = i >> 5, cc = i & 31;
            Ws[rr * 36 + cc] = f2tf32(W[(size_t)(o0 + rr) * C + k0 + cc]);
        }
        for (int i = tid; i < 32 * 64; i += 256) {
            int kk = i >> 6, nn = i & 63;
            Xs[kk * 72 + nn] = f2tf32(Xb[(size_t)(k0 + kk) * N + n0 + nn]);
        }
        __syncthreads();
#pragma unroll
        for (int ks = 0; ks < 4; ks++) {
            int kb = ks * 8;
            uint32_t a[4];
            a[0] = Ws[(r0 + gr) * 36 + kb + t];
            a[1] = Ws[(r0 + gr + 8) * 36 + kb + t];
            a[2] = Ws[(r0 + gr) * 36 + kb + t + 4];
            a[3] = Ws[(r0 + gr + 8) * 36 + kb + t + 4];
#pragma unroll
            for (int nt = 0; nt < 4; nt++) {
                int nb = c0 + nt * 8;
                uint32_t bb[2];
                bb[0] = Xs[(kb + t) * 72 + nb + gr];
                bb[1] = Xs[(kb + t + 4) * 72 + nb + gr];
                mma_tf32(acc[nt], a, bb);
            }
        }
        __syncthreads();
    }
    int o_a = o0 + r0 + gr, o_b = o_a + 8;
    float bv_a = bias[o_a], bv_b = bias[o_b];
    if (o0 < 512) {
        bool isq = (o0 < 256);
        float fs = isq ? SCALE : 1.0f;          // fold softmax scale into Q
        __nv_bfloat16* dst = isq ? g_q : g_k;
        int oc_a = o_a & 255, oc_b = o_b & 255;
#pragma unroll
        for (int nt = 0; nt < 4; nt++) {
            int n = n0 + c0 + nt * 8 + 2 * t;
            dst[((size_t)b * N + n)     * C + oc_a] = __float2bfloat16((acc[nt][0] + bv_a) * fs);
            dst[((size_t)b * N + n + 1) * C + oc_a] = __float2bfloat16((acc[nt][1] + bv_a) * fs);
            dst[((size_t)b * N + n)     * C + oc_b] = __float2bfloat16((acc[nt][2] + bv_b) * fs);
            dst[((size_t)b * N + n + 1) * C + oc_b] = __float2bfloat16((acc[nt][3] + bv_b) * fs);
        }
    } else {
        int oc_a = o_a - 512, oc_b = o_b - 512;
#pragma unroll
        for (int nt = 0; nt < 4; nt++) {
            int n = n0 + c0 + nt * 8 + 2 * t;
            __nv_bfloat162 va = __floats2bfloat162_rn(acc[nt][0] + bv_a, acc[nt][1] + bv_a);
            __nv_bfloat162 vb = __floats2bfloat162_rn(acc[nt][2] + bv_b, acc[nt][3] + bv_b);
            *(__nv_bfloat162*)&g_v[((size_t)b * C + oc_a) * N + n] = va;
            *(__nv_bfloat162*)&g_v[((size_t)b * C + oc_b) * N + n] = vb;
        }
    }
}

// ---------------- kernel 4: flash attention, Q-resident FA2 ------------------
// Br=128, Bc=64, 8 warps; warp w owns rows 16w..16w+15 (all 64 S cols).
// Q A-fragments resident in registers (loaded once). K/V staged full-tile into
// ONE union smem buffer (36.9KB). 4 barriers per j-tile.
__global__ __launch_bounds__(256, 1) void flash_kernel() {
    __shared__ __align__(16) uint32_t SBUF[256 * 36];   // 9216 u32 = 36,864B
    // K view: 64 rows x 132 u32 (256 bf16 + pad)  -> 8448 u32
    // V view: 256 ch  x 36 u32  (64 bf16 + pad)   -> 9216 u32
    // Q-stage view (prologue): 128 rows x 36 u32  -> 4608 u32

    int b  = blockIdx.y;
    int i0 = blockIdx.x * 128;
    const __nv_bfloat16* Qb = g_q + (size_t)b * N * C;
    const __nv_bfloat16* Kb = g_k + (size_t)b * N * C;
    const uint32_t* Vb32 = (const uint32_t*)(g_v + (size_t)b * C * N);

    int tid  = threadIdx.x;
    int warp = tid >> 5, lane = tid & 31;
    int gr = lane >> 2, t = lane & 3;
    int r0 = 16 * warp;

    int l15 = lane & 15, l7 = lane & 7;
    int hi16 = lane >> 4;
    int bsel = (lane >> 3) & 1;
    uint32_t sbase = smem_u32(SBUF);
    uint32_t qa_addr = sbase + 4u * ((r0 + l15) * 36 + 4 * hi16);
    uint32_t kb_addr = sbase + 4u * ((l7 + 8 * hi16) * 132 + 4 * bsel);
    uint32_t vb_addr = sbase + 4u * ((l7 + 8 * hi16) * 36 + 4 * bsel);

    // ---- prologue: load Q A-fragments into registers (16 k16-tiles) ----
    uint32_t qreg[16][4];
    for (int chunk = 0; chunk < 4; chunk++) {
#pragma unroll 1
        for (int i = tid; i < 1024; i += 256) {
            int rr = i >> 3, cc = i & 7;
            ((uint4*)(SBUF + rr * 36))[cc] =
                ((const uint4*)(Qb + (size_t)(i0 + rr) * C + chunk * 64))[cc];
        }
        __syncthreads();
#pragma unroll
        for (int ks = 0; ks < 4; ks++) {
            int kt = chunk * 4 + ks;
            ldsm_x4(qreg[kt][0], qreg[kt][1], qreg[kt][2], qreg[kt][3],
                    qa_addr + 32 * ks);
        }
        __syncthreads();
    }

    float O[32][4];
#pragma unroll
    for (int i = 0; i < 32; i++)
#pragma unroll
        for (int j = 0; j < 4; j++) O[i][j] = 0.f;
    float m0 = -3.4e38f, m1 = -3.4e38f, l0 = 0.f, l1 = 0.f;

    for (int j0 = 0; j0 < N; j0 += 64) {
        // ---------- stage K full tile (64 x 256 bf16) ----------
#pragma unroll 1
        for (int i = tid; i < 2048; i += 256) {
            int rr = i >> 5, cc = i & 31;
            ((uint4*)(SBUF + rr * 132))[cc] =
                ((const uint4*)(Kb + (size_t)(j0 + rr) * C))[cc];
        }
        __syncthreads();

        // ---------- S = Q K^T (Q from regs) ----------
        float accs[8][4];
#pragma unroll
        for (int i = 0; i < 8; i++)
#pragma unroll
            for (int j = 0; j < 4; j++) accs[i][j] = 0.f;
#pragma unroll
        for (int ks = 0; ks < 16; ks++) {
#pragma unroll
            for (int pr = 0; pr < 4; pr++) {
                uint32_t b0, b1, b2, b3;
                ldsm_x4(b0, b1, b2, b3, kb_addr + 8448 * pr + 32 * ks);
                mma_bf16(accs[2 * pr],     qreg[ks], b0, b1);
                mma_bf16(accs[2 * pr + 1], qreg[ks], b2, b3);
            }
        }
        __syncthreads();   // K reads done before V overwrites buffer

        // ---------- stage V full tile (256 ch x 64 seq) ----------
#pragma unroll 1
        for (int i = tid; i < 2048; i += 256) {
            int ch = i >> 3, q = i & 7;
            ((uint4*)(SBUF + ch * 36))[q] =
                ((const uint4*)(Vb32 + (size_t)ch * (N / 2) + (j0 >> 1)))[q];
        }

        // ---------- online softmax in registers (overlaps V loads) ----------
        float mx0 = -3.4e38f, mx1 = -3.4e38f;
#pragma unroll
        for (int j = 0; j < 8; j++) {
            mx0 = fmaxf(mx0, fmaxf(accs[j][0], accs[j][1]));
            mx1 = fmaxf(mx1, fmaxf(accs[j][2], accs[j][3]));
        }
        mx0 = fmaxf(mx0, __shfl_xor_sync(0xffffffffu, mx0, 1));
        mx0 = fmaxf(mx0, __shfl_xor_sync(0xffffffffu, mx0, 2));
        mx1 = fmaxf(mx1, __shfl_xor_sync(0xffffffffu, mx1, 1));
        mx1 = fmaxf(mx1, __shfl_xor_sync(0xffffffffu, mx1, 2));
        float mn0 = fmaxf(m0, mx0);
        float mn1 = fmaxf(m1, mx1);
        float al0 = __expf(m0 - mn0);
        float al1 = __expf(m1 - mn1);
        m0 = mn0; m1 = mn1;
        float s0 = 0.f, s1 = 0.f;
#pragma unroll
        for (int j = 0; j < 8; j++) {
            accs[j][0] = __expf(accs[j][0] - m0);
            accs[j][1] = __expf(accs[j][1] - m0);
            accs[j][2] = __expf(accs[j][2] - m1);
            accs[j][3] = __expf(accs[j][3] - m1);
            s0 += accs[j][0] + accs[j][1];
            s1 += accs[j][2] + accs[j][3];
        }
        s0 += __shfl_xor_sync(0xffffffffu, s0, 1);
        s0 += __shfl_xor_sync(0xffffffffu, s0, 2);
        s1 += __shfl_xor_sync(0xffffffffu, s1, 1);
        s1 += __shfl_xor_sync(0xffffffffu, s1, 2);
        l0 = l0 * al0 + s0;
        l1 = l1 * al1 + s1;
#pragma unroll
        for (int nt = 0; nt < 32; nt++) {
            O[nt][0] *= al0; O[nt][1] *= al0;
            O[nt][2] *= al1; O[nt][3] *= al1;
        }
        __syncthreads();   // V staged

        // ---------- O += P V (P from regs; full 64-seq k range) ----------
#pragma unroll
        for (int sub = 0; sub < 4; sub++) {
            uint32_t a[4];
            __nv_bfloat162 p0 = __floats2bfloat162_rn(accs[2 * sub][0], accs[2 * sub][1]);
            __nv_bfloat162 p1 = __floats2bfloat162_rn(accs[2 * sub][2], accs[2 * sub][3]);
            __nv_bfloat162 p2 = __floats2bfloat162_rn(accs[2 * sub + 1][0], accs[2 * sub + 1][1]);
            __nv_bfloat162 p3 = __floats2bfloat162_rn(accs[2 * sub + 1][2], accs[2 * sub + 1][3]);
            a[0] = *(uint32_t*)&p0;
            a[1] = *(uint32_t*)&p1;
            a[2] = *(uint32_t*)&p2;
            a[3] = *(uint32_t*)&p3;
#pragma unroll
            for (int ntp = 0; ntp < 16; ntp++) {
                uint32_t v0, v1, v2, v3;
                ldsm_x4(v0, v1, v2, v3, vb_addr + 2304 * ntp + 32 * sub);
                mma_bf16(O[2 * ntp],     a, v0, v1);
                mma_bf16(O[2 * ntp + 1], a, v2, v3);
            }
        }
        __syncthreads();   // V reads done before next K stage
    }

    // ---------- finalize ----------
    float inv0 = 1.0f / l0;
    float inv1 = 1.0f / l1;
    float* Ab = g_att + (size_t)b * N * C;
#pragma unroll
    for (int nt = 0; nt < 32; nt++) {
        int col = nt * 8 + 2 * t;
        float2 v0 = make_float2(O[nt][0] * inv0, O[nt][1] * inv0);
        float2 v1 = make_float2(O[nt][2] * inv1, O[nt][3] * inv1);
        *(float2*)&Ab[(size_t)(i0 + r0 + gr) * C + col]     = v0;
        *(float2*)&Ab[(size_t)(i0 + r0 + gr + 8) * C + col] = v1;
    }
}

// ---------------- kernel 5: proj GEMM + bias + residual, tf32 mma ------------
__global__ __launch_bounds__(256) void proj_gemm(const float* __restrict__ W,
                                                 const float* __restrict__ bias,
                                                 const float* __restrict__ x,
                                                 float* __restrict__ out) {
    __shared__ uint32_t Ws[64 * 36];
    __shared__ uint32_t Bs[32 * 68];
    int b  = blockIdx.z;
    int o0 = blockIdx.y * 64;
    int n0 = blockIdx.x * 64;
    const float* Ab = g_att + (size_t)b * N * C;

    int tid  = threadIdx.x;
    int warp = tid >> 5, lane = tid & 31;
    int gr = lane >> 2, t = lane & 3;
    int r0 = 16 * (warp & 3);
    int c0 = 32 * (warp >> 2);

    float acc[4][4] = {};
    for (int k0 = 0; k0 < C; k0 += 32) {
        for (int i = tid; i < 64 * 32; i += 256) {
            int rr = i >> 5, cc = i & 31;
            Ws[rr * 36 + cc] = f2tf32(W[(size_t)(o0 + rr) * C + k0 + cc]);
        }
        for (int i = tid; i < 64 * 32; i += 256) {
            int nn = i >> 5, kk = i & 31;
            Bs[kk * 68 + nn] = f2tf32(Ab[(size_t)(n0 + nn) * C + k0 + kk]);
        }
        __syncthreads();
#pragma unroll
        for (int ks = 0; ks < 4; ks++) {
            int kb = ks * 8;
            uint32_t a[4];
            a[0] = Ws[(r0 + gr) * 36 + kb + t];
            a[1] = Ws[(r0 + gr + 8) * 36 + kb + t];
            a[2] = Ws[(r0 + gr) * 36 + kb + t + 4];
            a[3] = Ws[(r0 + gr + 8) * 36 + kb + t + 4];
#pragma unroll
            for (int nt = 0; nt < 4; nt++) {
                int nb = c0 + nt * 8;
                uint32_t bb[2];
                bb[0] = Bs[(kb + t) * 68 + nb + gr];
                bb[1] = Bs[(kb + t + 4) * 68 + nb + gr];
                mma_tf32(acc[nt], a, bb);
            }
        }
        __syncthreads();
    }
    int o_a = o0 + r0 + gr, o_b = o_a + 8;
    float bv_a = bias[o_a], bv_b = bias[o_b];
#pragma unroll
    for (int nt = 0; nt < 4; nt++) {
        int n = n0 + c0 + nt * 8 + 2 * t;
        size_t ia = ((size_t)b * C + o_a) * N + n;
        size_t ib = ((size_t)b * C + o_b) * N + n;
        float2 xa = *(const float2*)&x[ia];
        float2 xb = *(const float2*)&x[ib];
        float2 oa = make_float2(acc[nt][0] + bv_a + xa.x, acc[nt][1] + bv_a + xa.y);
        float2 ob = make_float2(acc[nt][2] + bv_b + xb.x, acc[nt][3] + bv_b + xb.y);
        *(float2*)&out[ia] = oa;
        *(float2*)&out[ib] = ob;
    }
}

// ---------------- launch ------------------------------------------------------
extern "C" void kernel_launch(void* const* d_in, const int* in_sizes, int n_in,
                              void* d_out, int out_size) {
    const float* x    = (const float*)d_in[0];
    const float* gns  = (const float*)d_in[1];
    const float* gnb  = (const float*)d_in[2];
    const float* qkvw = (const float*)d_in[3];
    const float* qkvb = (const float*)d_in[4];
    const float* pw   = (const float*)d_in[5];
    const float* pb   = (const float*)d_in[6];
    float* out = (float*)d_out;

    gn_stats<<<B * G, 256>>>(x);
    gn_apply<<<(B * C * N / 4) / 256, 256>>>(x, gns, gnb);

    dim3 gq(N / 64, (3 * C) / 64, B);
    qkv_gemm<<<gq, 256>>>(qkvw, qkvb);

    dim3 gf(N / 128, B);
    flash_kernel<<<gf, 256>>>();

    dim3 gp(N / 64, C / 64, B);
    proj_gemm<<<gp, 256>>>(pw, pb, x, out);
}

// round 17
// speedup vs baseline: 1.3383x; 1.2323x over previous
#include <cuda_runtime.h>
#include <cuda_bf16.h>
#include <cstdint>

#define B 8
#define C 256
#define N 4096            // 64*64
#define G 8
#define CG 32             // channels per group
#define EPS 1e-5f
#define SCALE 0.0625f     // 1/sqrt(256)

// ---------------- scratch ----------------------------------------------------
__device__ float         g_xn[(size_t)B * C * N];   // groupnormed x, [b][c][n]
__device__ __nv_bfloat16 g_q[(size_t)B * N * C];    // Q [b][n][c]  (pre-scaled by SCALE)
__device__ __nv_bfloat16 g_k[(size_t)B * N * C];    // K [b][n][c]
__device__ __nv_bfloat16 g_v[(size_t)B * C * N];    // V [b][c][n]  (transposed)
__device__ float         g_att[(size_t)B * N * C];  // attention out [b][n][c]
__device__ float         g_mean[B * G];
__device__ float         g_rstd[B * G];

// ---------------- mma / ldmatrix / cp.async helpers ---------------------------
__device__ __forceinline__ uint32_t f2tf32(float x) {
    uint32_t r;
    asm("cvt.rna.tf32.f32 %0, %1;" : "=r"(r) : "f"(x));
    return r;
}

__device__ __forceinline__ void mma_tf32(float* d, const uint32_t* a, const uint32_t* b) {
    asm volatile(
        "mma.sync.aligned.m16n8k8.row.col.f32.tf32.tf32.f32 "
        "{%0,%1,%2,%3}, {%4,%5,%6,%7}, {%8,%9}, {%0,%1,%2,%3};\n"
        : "+f"(d[0]), "+f"(d[1]), "+f"(d[2]), "+f"(d[3])
        : "r"(a[0]), "r"(a[1]), "r"(a[2]), "r"(a[3]),
          "r"(b[0]), "r"(b[1]));
}

__device__ __forceinline__ void mma_bf16(float* d, const uint32_t* a,
                                         uint32_t b0, uint32_t b1) {
    asm volatile(
        "mma.sync.aligned.m16n8k16.row.col.f32.bf16.bf16.f32 "
        "{%0,%1,%2,%3}, {%4,%5,%6,%7}, {%8,%9}, {%0,%1,%2,%3};\n"
        : "+f"(d[0]), "+f"(d[1]), "+f"(d[2]), "+f"(d[3])
        : "r"(a[0]), "r"(a[1]), "r"(a[2]), "r"(a[3]),
          "r"(b0), "r"(b1));
}

__device__ __forceinline__ void ldsm_x4(uint32_t& r0, uint32_t& r1,
                                        uint32_t& r2, uint32_t& r3, uint32_t addr) {
    asm volatile("ldmatrix.sync.aligned.m8n8.x4.shared.b16 {%0,%1,%2,%3}, [%4];"
                 : "=r"(r0), "=r"(r1), "=r"(r2), "=r"(r3) : "r"(addr));
}

__device__ __forceinline__ uint32_t smem_u32(const void* p) {
    return (uint32_t)__cvta_generic_to_shared(p);
}

__device__ __forceinline__ void cp_async16(uint32_t saddr, const void* gptr) {
    asm volatile("cp.async.cg.shared.global [%0], [%1], 16;\n"
                 :: "r"(saddr), "l"(gptr));
}
#define CP_COMMIT() asm volatile("cp.async.commit_group;\n" ::: "memory")
#define CP_WAIT0()  asm volatile("cp.async.wait_group 0;\n" ::: "memory")
#define CP_WAIT1()  asm volatile("cp.async.wait_group 1;\n" ::: "memory")

// ---------------- kernel 1: groupnorm stats ----------------------------------
__global__ void gn_stats(const float* __restrict__ x) {
    int bg = blockIdx.x;
    const float4* p = (const float4*)(x + (size_t)bg * CG * N);
    float s = 0.f, ss = 0.f;
    for (int i = threadIdx.x; i < (CG * N) / 4; i += blockDim.x) {
        float4 v = p[i];
        s  += v.x + v.y + v.z + v.w;
        ss += v.x * v.x + v.y * v.y + v.z * v.z + v.w * v.w;
    }
    for (int o = 16; o > 0; o >>= 1) {
        s  += __shfl_down_sync(0xffffffffu, s, o);
        ss += __shfl_down_sync(0xffffffffu, ss, o);
    }
    __shared__ float rs[8], rss[8];
    int wid = threadIdx.x >> 5, lid = threadIdx.x & 31;
    if (lid == 0) { rs[wid] = s; rss[wid] = ss; }
    __syncthreads();
    if (threadIdx.x == 0) {
        float ts = 0.f, tss = 0.f;
        for (int i = 0; i < 8; i++) { ts += rs[i]; tss += rss[i]; }
        float inv = 1.0f / (float)(CG * N);
        float mean = ts * inv;
        float var = tss * inv - mean * mean;
        g_mean[bg] = mean;
        g_rstd[bg] = rsqrtf(var + EPS);
    }
}

// ---------------- kernel 2: groupnorm apply ----------------------------------
__global__ void gn_apply(const float* __restrict__ x,
                         const float* __restrict__ sc,
                         const float* __restrict__ bi) {
    int i = blockIdx.x * blockDim.x + threadIdx.x;
    int e = i << 2;
    int c = (e >> 12) & (C - 1);
    int bg = e >> 17;
    float m = g_mean[bg], r = g_rstd[bg];
    float a = sc[c] * r;
    float b = bi[c] - m * a;
    float4 v = ((const float4*)x)[i];
    float4 o;
    o.x = v.x * a + b; o.y = v.y * a + b; o.z = v.z * a + b; o.w = v.w * a + b;
    ((float4*)g_xn)[i] = o;
}

// ---------------- kernel 3: QKV GEMM, tf32 mma; writes bf16 ------------------
__global__ __launch_bounds__(256) void qkv_gemm(const float* __restrict__ W,
                                                const float* __restrict__ bias) {
    __shared__ uint32_t Ws[64 * 36];
    __shared__ uint32_t Xs[32 * 72];
    int b  = blockIdx.z;
    int o0 = blockIdx.y * 64;
    int n0 = blockIdx.x * 64;
    const float* Xb = g_xn + (size_t)b * C * N;

    int tid  = threadIdx.x;
    int warp = tid >> 5, lane = tid & 31;
    int gr = lane >> 2, t = lane & 3;
    int r0 = 16 * (warp & 3);
    int c0 = 32 * (warp >> 2);

    float acc[4][4] = {};
    for (int k0 = 0; k0 < C; k0 += 32) {
        for (int i = tid; i < 64 * 32; i += 256) {
            int rr = i >> 5, cc = i & 31;
            Ws[rr * 36 + cc] = f2tf32(W[(size_t)(o0 + rr) * C + k0 + cc]);
        }
        for (int i = tid; i < 32 * 64; i += 256) {
            int kk = i >> 6, nn = i & 63;
            Xs[kk * 72 + nn] = f2tf32(Xb[(size_t)(k0 + kk) * N + n0 + nn]);
        }
        __syncthreads();
#pragma unroll
        for (int ks = 0; ks < 4; ks++) {
            int kb = ks * 8;
            uint32_t a[4];
            a[0] = Ws[(r0 + gr) * 36 + kb + t];
            a[1] = Ws[(r0 + gr + 8) * 36 + kb + t];
            a[2] = Ws[(r0 + gr) * 36 + kb + t + 4];
            a[3] = Ws[(r0 + gr + 8) * 36 + kb + t + 4];
#pragma unroll
            for (int nt = 0; nt < 4; nt++) {
                int nb = c0 + nt * 8;
                uint32_t bb[2];
                bb[0] = Xs[(kb + t) * 72 + nb + gr];
                bb[1] = Xs[(kb + t + 4) * 72 + nb + gr];
                mma_tf32(acc[nt], a, bb);
            }
        }
        __syncthreads();
    }
    int o_a = o0 + r0 + gr, o_b = o_a + 8;
    float bv_a = bias[o_a], bv_b = bias[o_b];
    if (o0 < 512) {
        bool isq = (o0 < 256);
        float fs = isq ? SCALE : 1.0f;          // fold softmax scale into Q
        __nv_bfloat16* dst = isq ? g_q : g_k;
        int oc_a = o_a & 255, oc_b = o_b & 255;
#pragma unroll
        for (int nt = 0; nt < 4; nt++) {
            int n = n0 + c0 + nt * 8 + 2 * t;
            dst[((size_t)b * N + n)     * C + oc_a] = __float2bfloat16((acc[nt][0] + bv_a) * fs);
            dst[((size_t)b * N + n + 1) * C + oc_a] = __float2bfloat16((acc[nt][1] + bv_a) * fs);
            dst[((size_t)b * N + n)     * C + oc_b] = __float2bfloat16((acc[nt][2] + bv_b) * fs);
            dst[((size_t)b * N + n + 1) * C + oc_b] = __float2bfloat16((acc[nt][3] + bv_b) * fs);
        }
    } else {
        int oc_a = o_a - 512, oc_b = o_b - 512;
#pragma unroll
        for (int nt = 0; nt < 4; nt++) {
            int n = n0 + c0 + nt * 8 + 2 * t;
            __nv_bfloat162 va = __floats2bfloat162_rn(acc[nt][0] + bv_a, acc[nt][1] + bv_a);
            __nv_bfloat162 vb = __floats2bfloat162_rn(acc[nt][2] + bv_b, acc[nt][3] + bv_b);
            *(__nv_bfloat162*)&g_v[((size_t)b * C + oc_a) * N + n] = va;
            *(__nv_bfloat162*)&g_v[((size_t)b * C + oc_b) * N + n] = vb;
        }
    }
}

// ---------------- kernel 4: flash attention, cp.async pipelined (R10 base) ----
// Br=Bc=64, 8 warps. Warp roles identical to R10: r0=16*(w&3) rows,
// cs=32*(w>>2) S-cols, co=128*(w>>2) O-cols. Softmax: 4 adjacent lanes/row.
// QK staged in 32-chan chunks, double buffered via cp.async.
// V staged in 4x16-seq chunks ping-ponging QK area <-> Ps area.
__global__ __launch_bounds__(256, 2) void flash_kernel() {
    __shared__ __align__(16) uint32_t QKb[5120];  // 2 bufs: [0..2559],[2560..5119]; each: Q 64x20 @0, K 64x20 @1280
    __shared__ __align__(16) uint32_t PsVs[4352]; // Ps 64x68 f32 ; V buf B (3072) aliased
    __shared__ __align__(16) uint32_t Pp[2304];   // packed bf16 P, 64x36
    __shared__ float rowm[64], rowl[64], rowa[64];

    int b  = blockIdx.y;
    int i0 = blockIdx.x * 64;
    const __nv_bfloat16* Qb = g_q + (size_t)b * N * C;
    const __nv_bfloat16* Kb = g_k + (size_t)b * N * C;
    const uint32_t* Vb32 = (const uint32_t*)(g_v + (size_t)b * C * N);

    int tid  = threadIdx.x;
    int warp = tid >> 5, lane = tid & 31;
    int gr = lane >> 2, t = lane & 3;
    int r0 = 16 * (warp & 3);
    int cs = 32 * (warp >> 2);
    int co = 128 * (warp >> 2);
    int smrow = tid >> 2, smseg = tid & 3;

    int l15 = lane & 15, l7 = lane & 7;
    int hi16 = lane >> 4;
    int bsel = (lane >> 3) & 1;

    uint32_t sQK  = smem_u32(QKb);
    uint32_t sPsV = smem_u32(PsVs);
    uint32_t sPp  = smem_u32(Pp);
    float* Psf = (float*)PsVs;

    // byte offsets within a QK chunk buffer
    uint32_t qa_off = 4u * ((r0 + l15) * 20 + 4 * hi16);
    uint32_t kb_off = 5120u + 4u * ((cs + l7 + 8 * hi16) * 20 + 4 * bsel);
    // V fragment offset within a V buffer (stride 12 u32)
    uint32_t vb_off = 4u * ((co + l7 + 8 * hi16) * 12 + 4 * bsel);
    uint32_t pa_addr = sPp + 4u * ((r0 + l15) * 36 + 4 * hi16);

    // staging index precompute
    int su  = tid;            // QK: 2 transfers (su, su+256)
    int qrow = (su & 255) >> 2, qseg = su & 3;

    float acco[16][4];
#pragma unroll
    for (int i = 0; i < 16; i++)
#pragma unroll
        for (int j = 0; j < 4; j++) acco[i][j] = 0.f;

    if (tid < 64) { rowm[tid] = -3.4e38f; rowl[tid] = 0.f; }

    // ---- prologue: prefetch QK chunk 0 of j0=0 into buf 0 ----
    {
        cp_async16(sQK + 4u * (qrow * 20 + qseg * 4),
                   Qb + (size_t)(i0 + qrow) * C + qseg * 8);
        cp_async16(sQK + 4u * (1280 + qrow * 20 + qseg * 4),
                   Kb + (size_t)qrow * C + qseg * 8);
        CP_COMMIT();
    }

    for (int j0 = 0; j0 < N; j0 += 64) {
        // ================= S phase: 8 chunks of 32 channels =================
        float accs[4][4];
#pragma unroll
        for (int i = 0; i < 4; i++)
#pragma unroll
            for (int j = 0; j < 4; j++) accs[i][j] = 0.f;

        for (int c = 0; c < 8; c++) {
            CP_WAIT0();           // chunk c arrived (only pending group)
            __syncthreads();
            if (c < 7) {          // prefetch chunk c+1
                uint32_t dbase = sQK + 10240u * ((c + 1) & 1);
                int k0n = 32 * (c + 1);
                cp_async16(dbase + 4u * (qrow * 20 + qseg * 4),
                           Qb + (size_t)(i0 + qrow) * C + k0n + qseg * 8);
                cp_async16(dbase + 4u * (1280 + qrow * 20 + qseg * 4),
                           Kb + (size_t)(j0 + qrow) * C + k0n + qseg * 8);
                CP_COMMIT();
            }
            uint32_t base = sQK + 10240u * (c & 1);
#pragma unroll
            for (int ks = 0; ks < 2; ks++) {
                uint32_t a[4];
                ldsm_x4(a[0], a[1], a[2], a[3], base + qa_off + 32 * ks);
                uint32_t b0, b1, b2, b3, b4, b5, b6, b7;
                ldsm_x4(b0, b1, b2, b3, base + kb_off + 32 * ks);          // nt 0,1
                ldsm_x4(b4, b5, b6, b7, base + kb_off + 1280 + 32 * ks);   // nt 2,3
                mma_bf16(accs[0], a, b0, b1);
                mma_bf16(accs[1], a, b2, b3);
                mma_bf16(accs[2], a, b4, b5);
                mma_bf16(accs[3], a, b6, b7);
            }
        }
        __syncthreads();          // S done; QK area dead

        // ---- issue V chunk 0 -> QK area; then store S -> Ps ----
        {
            int ch = tid >> 1, seg = tid & 1;       // 512 transfers over 2 iters
            const uint32_t* vsrc = Vb32 + (size_t)ch * (N / 2) + (j0 >> 1);
            cp_async16(sQK + 4u * (ch * 12 + seg * 4), vsrc + seg * 4);
            int ch2 = (tid + 256) >> 1, seg2 = (tid + 256) & 1;
            const uint32_t* vsrc2 = Vb32 + (size_t)ch2 * (N / 2) + (j0 >> 1);
            cp_async16(sQK + 4u * (ch2 * 12 + seg2 * 4), vsrc2 + seg2 * 4);
            CP_COMMIT();
        }
#pragma unroll
        for (int nt = 0; nt < 4; nt++) {
            int col = cs + nt * 8 + 2 * t;
            float2 v0 = make_float2(accs[nt][0], accs[nt][1]);
            float2 v1 = make_float2(accs[nt][2], accs[nt][3]);
            *(float2*)&Psf[(r0 + gr) * 68 + col]     = v0;
            *(float2*)&Psf[(r0 + gr + 8) * 68 + col] = v1;
        }
        __syncthreads();          // Ps visible

        // ---- fused online softmax (Q pre-scaled; no SCALE here) ----
        {
            float mprev = rowm[smrow];
            float vals[16];
            float mx = mprev;
            const float* sr = Psf + smrow * 68 + smseg * 16;
#pragma unroll
            for (int j = 0; j < 16; j++) {
                vals[j] = sr[j];
                mx = fmaxf(mx, vals[j]);
            }
            mx = fmaxf(mx, __shfl_xor_sync(0xffffffffu, mx, 1));
            mx = fmaxf(mx, __shfl_xor_sync(0xffffffffu, mx, 2));
            float s = 0.f;
#pragma unroll
            for (int j = 0; j < 16; j++) {
                vals[j] = __expf(vals[j] - mx);
                s += vals[j];
            }
            uint32_t* pr = Pp + smrow * 36 + smseg * 8;
#pragma unroll
            for (int p = 0; p < 8; p++) {
                __nv_bfloat162 pv = __floats2bfloat162_rn(vals[2 * p], vals[2 * p + 1]);
                pr[p] = *(uint32_t*)&pv;
            }
            s += __shfl_xor_sync(0xffffffffu, s, 1);
            s += __shfl_xor_sync(0xffffffffu, s, 2);
            if (smseg == 0) {
                float alpha = __expf(mprev - mx);
                rowa[smrow] = alpha;
                rowm[smrow] = mx;
                rowl[smrow] = rowl[smrow] * alpha + s;
            }
        }
        __syncthreads();          // Pp/stats visible; Ps dead

        // ---- issue V chunk 1 -> Ps area ----
        {
            int ch = tid >> 1, seg = tid & 1;
            const uint32_t* vsrc = Vb32 + (size_t)ch * (N / 2) + ((j0 + 16) >> 1);
            cp_async16(sPsV + 4u * (ch * 12 + seg * 4), vsrc + seg * 4);
            int ch2 = (tid + 256) >> 1, seg2 = (tid + 256) & 1;
            const uint32_t* vsrc2 = Vb32 + (size_t)ch2 * (N / 2) + ((j0 + 16) >> 1);
            cp_async16(sPsV + 4u * (ch2 * 12 + seg2 * 4), vsrc2 + seg2 * 4);
            CP_COMMIT();
        }

        // ---- rescale O by alpha ----
        float al0 = rowa[r0 + gr], al1 = rowa[r0 + gr + 8];
#pragma unroll
        for (int nt = 0; nt < 16; nt++) {
            acco[nt][0] *= al0; acco[nt][1] *= al0;
            acco[nt][2] *= al1; acco[nt][3] *= al1;
        }

        // ---- PV chunks 0..3 (each 16 seq = one k16 step) ----
#pragma unroll
        for (int vc = 0; vc < 4; vc++) {
            CP_WAIT1();
            __syncthreads();      // V chunk vc visible
            uint32_t vbase = (vc & 1) ? sPsV : sQK;
            uint32_t a[4];
            ldsm_x4(a[0], a[1], a[2], a[3], pa_addr + 32 * vc);
#pragma unroll
            for (int ntp = 0; ntp < 8; ntp++) {
                uint32_t v0, v1, v2, v3;
                ldsm_x4(v0, v1, v2, v3, vbase + vb_off + 768 * ntp);
                mma_bf16(acco[2 * ntp],     a, v0, v1);
                mma_bf16(acco[2 * ntp + 1], a, v2, v3);
            }
            __syncthreads();      // reads done; buffer reusable
            if (vc == 0) {
                // issue V2 -> QK area
                int ch = tid >> 1, seg = tid & 1;
                const uint32_t* vsrc = Vb32 + (size_t)ch * (N / 2) + ((j0 + 32) >> 1);
                cp_async16(sQK + 4u * (ch * 12 + seg * 4), vsrc + seg * 4);
                int ch2 = (tid + 256) >> 1, seg2 = (tid + 256) & 1;
                const uint32_t* vsrc2 = Vb32 + (size_t)ch2 * (N / 2) + ((j0 + 32) >> 1);
                cp_async16(sQK + 4u * (ch2 * 12 + seg2 * 4), vsrc2 + seg2 * 4);
                CP_COMMIT();
            } else if (vc == 1) {
                // issue V3 -> Ps area
                int ch = tid >> 1, seg = tid & 1;
                const uint32_t* vsrc = Vb32 + (size_t)ch * (N / 2) + ((j0 + 48) >> 1);
                cp_async16(sPsV + 4u * (ch * 12 + seg * 4), vsrc + seg * 4);
                int ch2 = (tid + 256) >> 1, seg2 = (tid + 256) & 1;
                const uint32_t* vsrc2 = Vb32 + (size_t)ch2 * (N / 2) + ((j0 + 48) >> 1);
                cp_async16(sPsV + 4u * (ch2 * 12 + seg2 * 4), vsrc2 + seg2 * 4);
                CP_COMMIT();
            } else if (vc == 2) {
                // QK area free: prefetch next j-tile's chunk 0 -> buf 0
                if (j0 + 64 < N) {
                    cp_async16(sQK + 4u * (qrow * 20 + qseg * 4),
                               Qb + (size_t)(i0 + qrow) * C + qseg * 8);
                    cp_async16(sQK + 4u * (1280 + qrow * 20 + qseg * 4),
                               Kb + (size_t)(j0 + 64 + qrow) * C + qseg * 8);
                    CP_COMMIT();
                } else {
                    CP_COMMIT();   // empty group keeps per-thread accounting uniform
                }
            }
        }
    }

    // ---------- finalize ----------
    CP_WAIT0();
    float inv0 = 1.0f / rowl[r0 + gr];
    float inv1 = 1.0f / rowl[r0 + gr + 8];
    float* Ab = g_att + (size_t)b * N * C;
#pragma unroll
    for (int nt = 0; nt < 16; nt++) {
        int col = co + nt * 8 + 2 * t;
        float2 v0 = make_float2(acco[nt][0] * inv0, acco[nt][1] * inv0);
        float2 v1 = make_float2(acco[nt][2] * inv1, acco[nt][3] * inv1);
        *(float2*)&Ab[(size_t)(i0 + r0 + gr) * C + col]     = v0;
        *(float2*)&Ab[(size_t)(i0 + r0 + gr + 8) * C + col] = v1;
    }
}

// ---------------- kernel 5: proj GEMM + bias + residual, tf32 mma ------------
__global__ __launch_bounds__(256) void proj_gemm(const float* __restrict__ W,
                                                 const float* __restrict__ bias,
                                                 const float* __restrict__ x,
                                                 float* __restrict__ out) {
    __shared__ uint32_t Ws[64 * 36];
    __shared__ uint32_t Bs[32 * 68];
    int b  = blockIdx.z;
    int o0 = blockIdx.y * 64;
    int n0 = blockIdx.x * 64;
    const float* Ab = g_att + (size_t)b * N * C;

    int tid  = threadIdx.x;
    int warp = tid >> 5, lane = tid & 31;
    int gr = lane >> 2, t = lane & 3;
    int r0 = 16 * (warp & 3);
    int c0 = 32 * (warp >> 2);

    float acc[4][4] = {};
    for (int k0 = 0; k0 < C; k0 += 32) {
        for (int i = tid; i < 64 * 32; i += 256) {
            int rr = i >> 5, cc = i & 31;
            Ws[rr * 36 + cc] = f2tf32(W[(size_t)(o0 + rr) * C + k0 + cc]);
        }
        for (int i = tid; i < 64 * 32; i += 256) {
            int nn = i >> 5, kk = i & 31;
            Bs[kk * 68 + nn] = f2tf32(Ab[(size_t)(n0 + nn) * C + k0 + kk]);
        }
        __syncthreads();
#pragma unroll
        for (int ks = 0; ks < 4; ks++) {
            int kb = ks * 8;
            uint32_t a[4];
            a[0] = Ws[(r0 + gr) * 36 + kb + t];
            a[1] = Ws[(r0 + gr + 8) * 36 + kb + t];
            a[2] = Ws[(r0 + gr) * 36 + kb + t + 4];
            a[3] = Ws[(r0 + gr + 8) * 36 + kb + t + 4];
#pragma unroll
            for (int nt = 0; nt < 4; nt++) {
                int nb = c0 + nt * 8;
                uint32_t bb[2];
                bb[0] = Bs[(kb + t) * 68 + nb + gr];
                bb[1] = Bs[(kb + t + 4) * 68 + nb + gr];
                mma_tf32(acc[nt], a, bb);
            }
        }
        __syncthreads();
    }
    int o_a = o0 + r0 + gr, o_b = o_a + 8;
    float bv_a = bias[o_a], bv_b = bias[o_b];
#pragma unroll
    for (int nt = 0; nt < 4; nt++) {
        int n = n0 + c0 + nt * 8 + 2 * t;
        size_t ia = ((size_t)b * C + o_a) * N + n;
        size_t ib = ((size_t)b * C + o_b) * N + n;
        float2 xa = *(const float2*)&x[ia];
        float2 xb = *(const float2*)&x[ib];
        float2 oa = make_float2(acc[nt][0] + bv_a + xa.x, acc[nt][1] + bv_a + xa.y);
        float2 ob = make_float2(acc[nt][2] + bv_b + xb.x, acc[nt][3] + bv_b + xb.y);
        *(float2*)&out[ia] = oa;
        *(float2*)&out[ib] = ob;
    }
}

// ---------------- launch ------------------------------------------------------
extern "C" void kernel_launch(void* const* d_in, const int* in_sizes, int n_in,
                              void* d_out, int out_size) {
    const float* x    = (const float*)d_in[0];
    const float* gns  = (const float*)d_in[1];
    const float* gnb  = (const float*)d_in[2];
    const float* qkvw = (const float*)d_in[3];
    const float* qkvb = (const float*)d_in[4];
    const float* pw   = (const float*)d_in[5];
    const float* pb   = (const float*)d_in[6];
    float* out = (float*)d_out;

    gn_stats<<<B * G, 256>>>(x);
    gn_apply<<<(B * C * N / 4) / 256, 256>>>(x, gns, gnb);

    dim3 gq(N / 64, (3 * C) / 64, B);
    qkv_gemm<<<gq, 256>>>(qkvw, qkvb);

    dim3 gf(N / 64, B);
    flash_kernel<<<gf, 256>>>();

    dim3 gp(N / 64, C / 64, B);
    proj_gemm<<<gp, 256>>>(pw, pb, x, out);
}